// round 2
// baseline (speedup 1.0000x reference)
#include <cuda_runtime.h>
#include <cuda_bf16.h>

#define N_NODES 100000
#define N_EDGES 1600000
#define D 128

// Scratch accumulator: acc = ego + scatter_add(messages). 51.2 MB.
__device__ float g_acc[N_NODES * D];
// Index-dtype flag: 1 if edge_index is int64, 0 if int32.
__device__ int g_is64;

// ---------------------------------------------------------------------------
// Kernel 0: detect edge_index dtype. JAX without x64 silently emits int32
// even when the reference asks for int64. An int32 buffer misread as int64
// packs two indices per word -> values >= 2^32 (since indices are mostly
// nonzero). Sample 64 values; all in range => genuinely int64.
// ---------------------------------------------------------------------------
__global__ void detect_kernel(const long long* __restrict__ ei) {
    int ok = 1;
#pragma unroll 1
    for (int i = 0; i < 64; i++) {
        long long v = ei[i];
        if (v < 0 || v >= N_NODES) { ok = 0; break; }
    }
    g_is64 = ok;
}

// ---------------------------------------------------------------------------
// Kernel 1: acc = ego  (so the scatter adds produce ego + side directly)
// ---------------------------------------------------------------------------
__global__ void init_acc_kernel(const float* __restrict__ ego) {
    int i = blockIdx.x * blockDim.x + threadIdx.x;   // float4 index
    const int n4 = N_NODES * D / 4;
    if (i < n4) {
        reinterpret_cast<float4*>(g_acc)[i] =
            reinterpret_cast<const float4*>(ego)[i];
    }
}

// ---------------------------------------------------------------------------
// Kernel 2: scatter. One warp per edge; lane handles one float4 (D=128 = 32x4).
//   acc[dst] += w * ego[src]
// red.global.add.v4.f32 (REDG, no return) quarters the atomic op count.
// ---------------------------------------------------------------------------
__global__ void scatter_kernel(const float* __restrict__ ego,
                               const void* __restrict__ edge_index,
                               const float* __restrict__ edge_weight) {
    int gid  = blockIdx.x * blockDim.x + threadIdx.x;
    int lane = gid & 31;
    int e    = gid >> 5;
    if (e >= N_EDGES) return;

    long long dst, src;
    if (g_is64) {
        const long long* p = (const long long*)edge_index;
        dst = p[e];             // edge_index[0, e]
        src = p[N_EDGES + e];   // edge_index[1, e]
    } else {
        const int* p = (const int*)edge_index;
        dst = p[e];
        src = p[N_EDGES + e];
    }
    // Guard: wrong dtype guess fails correctness instead of crashing.
    if ((unsigned long long)dst >= N_NODES ||
        (unsigned long long)src >= N_NODES) return;

    float w = edge_weight[e];

    const float4 v = *reinterpret_cast<const float4*>(ego + src * D + lane * 4);
    float mx = v.x * w, my = v.y * w, mz = v.z * w, mw = v.w * w;

    float* p = g_acc + dst * D + lane * 4;
    asm volatile("red.global.add.v4.f32 [%0], {%1, %2, %3, %4};"
                 :: "l"(p), "f"(mx), "f"(my), "f"(mz), "f"(mw)
                 : "memory");
}

// ---------------------------------------------------------------------------
// Kernel 3: out = leaky_relu(acc @ W^T + b)
//   h[i,j] = sum_k acc[i,k] * W[j,k]   (W row-major [128,128])
// Tile: 64 rows x 128 cols per block, 256 threads, thread tile 8x4.
// W tile stored k-major (transposed) in smem -> LDS.128 reads, conflict-free.
// X reads are warp-broadcast (same address across lanes).
// ---------------------------------------------------------------------------
#define BM 64
#define BK 32
#define XPAD 36   // 64 x 36 floats
#define WPAD 132  // 32 x 132 floats (row = one k, 128 cols + pad)

__global__ void __launch_bounds__(256, 4)
gemm_kernel(const float* __restrict__ W,
            const float* __restrict__ bias,
            float* __restrict__ out) {
    __shared__ float Xs[BM * XPAD];      // Xs[r][k]
    __shared__ float Wst[BK * WPAD];     // Wst[k][j]

    const int tid = threadIdx.x;
    const int tc  = tid & 31;    // col group: cols tc*4 .. tc*4+3
    const int tr  = tid >> 5;    // row group: rows tr*8 .. tr*8+7
    const int block_row = blockIdx.x * BM;

    float acc[8][4];
#pragma unroll
    for (int i = 0; i < 8; i++)
#pragma unroll
        for (int j = 0; j < 4; j++) acc[i][j] = 0.0f;

    for (int k0 = 0; k0 < D; k0 += BK) {
        // --- load X tile: 64 rows x 32 cols = 512 float4, 2 per thread ---
#pragma unroll
        for (int t = 0; t < 2; t++) {
            int i  = tid + t * 256;
            int r  = i >> 3;          // 0..63
            int c4 = i & 7;           // 0..7 (float4 within 32 cols)
            int row = block_row + r;
            float4 v = make_float4(0.f, 0.f, 0.f, 0.f);
            if (row < N_NODES)
                v = *reinterpret_cast<const float4*>(g_acc + row * D + k0 + c4 * 4);
            *reinterpret_cast<float4*>(&Xs[r * XPAD + c4 * 4]) = v;
        }
        // --- load W tile transposed: W[j][k0+k] -> Wst[k][j] ---
        // 128 rows(j) x 32 cols(k) = 1024 float4, 4 per thread
#pragma unroll
        for (int t = 0; t < 4; t++) {
            int i  = tid + t * 256;
            int j  = i >> 3;          // 0..127
            int c4 = i & 7;           // 0..7
            float4 v = *reinterpret_cast<const float4*>(W + j * D + k0 + c4 * 4);
            Wst[(c4 * 4 + 0) * WPAD + j] = v.x;
            Wst[(c4 * 4 + 1) * WPAD + j] = v.y;
            Wst[(c4 * 4 + 2) * WPAD + j] = v.z;
            Wst[(c4 * 4 + 3) * WPAD + j] = v.w;
        }
        __syncthreads();

#pragma unroll
        for (int k = 0; k < BK; k++) {
            float4 wv = *reinterpret_cast<const float4*>(&Wst[k * WPAD + tc * 4]);
            float xv[8];
#pragma unroll
            for (int i = 0; i < 8; i++)
                xv[i] = Xs[(tr * 8 + i) * XPAD + k];   // warp broadcast
#pragma unroll
            for (int i = 0; i < 8; i++) {
                acc[i][0] = fmaf(xv[i], wv.x, acc[i][0]);
                acc[i][1] = fmaf(xv[i], wv.y, acc[i][1]);
                acc[i][2] = fmaf(xv[i], wv.z, acc[i][2]);
                acc[i][3] = fmaf(xv[i], wv.w, acc[i][3]);
            }
        }
        __syncthreads();
    }

    // epilogue: + bias, leaky relu, store
    const float4 bv = *reinterpret_cast<const float4*>(bias + tc * 4);
#pragma unroll
    for (int i = 0; i < 8; i++) {
        int row = block_row + tr * 8 + i;
        if (row < N_NODES) {
            float4 o;
            o.x = acc[i][0] + bv.x;
            o.y = acc[i][1] + bv.y;
            o.z = acc[i][2] + bv.z;
            o.w = acc[i][3] + bv.w;
            o.x = o.x > 0.f ? o.x : 0.01f * o.x;
            o.y = o.y > 0.f ? o.y : 0.01f * o.y;
            o.z = o.z > 0.f ? o.z : 0.01f * o.z;
            o.w = o.w > 0.f ? o.w : 0.01f * o.w;
            *reinterpret_cast<float4*>(out + row * D + tc * 4) = o;
        }
    }
}

// ---------------------------------------------------------------------------
extern "C" void kernel_launch(void* const* d_in, const int* in_sizes, int n_in,
                              void* d_out, int out_size) {
    const float* ego = (const float*)d_in[0];   // [100000,128] f32
    const void*  ei  = d_in[1];                 // [2,1600000] i32 or i64
    const float* ew  = (const float*)d_in[2];   // [1600000] f32
    const float* W   = (const float*)d_in[3];   // [128,128] f32
    const float* b   = (const float*)d_in[4];   // [128] f32
    float* out = (float*)d_out;

    // 0) detect index dtype
    detect_kernel<<<1, 1>>>((const long long*)ei);
    // 1) acc = ego
    {
        int n4 = N_NODES * D / 4;
        init_acc_kernel<<<(n4 + 255) / 256, 256>>>(ego);
    }
    // 2) scatter-add messages
    {
        long long total = (long long)N_EDGES * 32;
        int blocks = (int)((total + 255) / 256);
        scatter_kernel<<<blocks, 256>>>(ego, ei, ew);
    }
    // 3) GEMM + bias + leaky relu
    {
        int blocks = (N_NODES + BM - 1) / BM;
        gemm_kernel<<<blocks, 256>>>(W, b, out);
    }
}

// round 3
// speedup vs baseline: 1.2131x; 1.2131x over previous
#include <cuda_runtime.h>
#include <cuda_bf16.h>
#include <cstdint>

#define N_NODES 100000
#define N_EDGES 1600000
#define D 128

// Scratch accumulator: acc = ego + scatter_add(messages). 51.2 MB.
__device__ float g_acc[N_NODES * D];
// Index-dtype flag: 1 if edge_index is int64, 0 if int32.
__device__ int g_is64;

// ---------------------------------------------------------------------------
// Kernel 0: detect edge_index dtype (one warp, parallel probe + ballot).
// int32 data misread as int64 packs the next index into the high word ->
// value >= 2^32 with prob ~(1-1e-5) per sample; 32 samples => certain.
// ---------------------------------------------------------------------------
__global__ void detect_kernel(const long long* __restrict__ ei) {
    long long v = ei[threadIdx.x];
    unsigned bad = __ballot_sync(0xffffffffu,
                                 (unsigned long long)v >= (unsigned long long)N_NODES);
    if (threadIdx.x == 0) g_is64 = (bad == 0u);
}

// ---------------------------------------------------------------------------
// Kernel 1: acc = ego
// ---------------------------------------------------------------------------
__global__ void init_acc_kernel(const float* __restrict__ ego) {
    int i = blockIdx.x * blockDim.x + threadIdx.x;
    const int n4 = N_NODES * D / 4;
    if (i < n4) {
        reinterpret_cast<float4*>(g_acc)[i] =
            reinterpret_cast<const float4*>(ego)[i];
    }
}

// ---------------------------------------------------------------------------
// Kernel 2: scatter. One warp per edge; lane handles one float4.
// Edge arrays are streamed (__ldcs, read-once) so they don't evict the
// L2-resident ego/acc working set. REDG v4 for the adds.
// ---------------------------------------------------------------------------
__global__ void scatter_kernel(const float* __restrict__ ego,
                               const void* __restrict__ edge_index,
                               const float* __restrict__ edge_weight) {
    int gid  = blockIdx.x * blockDim.x + threadIdx.x;
    int lane = gid & 31;
    int e    = gid >> 5;
    if (e >= N_EDGES) return;

    long long dst, src;
    if (g_is64) {
        const long long* p = (const long long*)edge_index;
        dst = __ldcs(p + e);
        src = __ldcs(p + N_EDGES + e);
    } else {
        const int* p = (const int*)edge_index;
        dst = __ldcs(p + e);
        src = __ldcs(p + N_EDGES + e);
    }
    if ((unsigned long long)dst >= N_NODES ||
        (unsigned long long)src >= N_NODES) return;

    float w = __ldcs(edge_weight + e);

    const float4 v = *reinterpret_cast<const float4*>(ego + src * D + lane * 4);
    float mx = v.x * w, my = v.y * w, mz = v.z * w, mw = v.w * w;

    float* p = g_acc + dst * D + lane * 4;
    asm volatile("red.global.add.v4.f32 [%0], {%1, %2, %3, %4};"
                 :: "l"(p), "f"(mx), "f"(my), "f"(mz), "f"(mw)
                 : "memory");
}

// ---------------------------------------------------------------------------
// Kernel 3: out = leaky_relu(acc @ W^T + b) via tf32 mma.sync.m16n8k8.
//   Block tile 128x128, 8 warps (4m x 2n), warp tile 32x64.
//   Xs[128][36] (m,k), Ws[32][136] (k,n) — strides chosen conflict-free for
//   the fragment access patterns (36%32=4 with 8 rows x 4 cols; 136%32=8
//   with 4 k x 8 n -> 32 distinct banks each).
// ---------------------------------------------------------------------------
#define GBM 128
#define GBK 32
#define XS_STRIDE 36
#define WS_STRIDE 136

__device__ __forceinline__ uint32_t f2tf32(float f) {
    uint32_t u;
    asm("cvt.rna.tf32.f32 %0, %1;" : "=r"(u) : "f"(f));
    return u;
}

__device__ __forceinline__ void mma_tf32(float d[4], const uint32_t a[4],
                                         const uint32_t b[2]) {
    asm volatile(
        "mma.sync.aligned.m16n8k8.row.col.f32.tf32.tf32.f32 "
        "{%0,%1,%2,%3}, {%4,%5,%6,%7}, {%8,%9}, {%0,%1,%2,%3};"
        : "+f"(d[0]), "+f"(d[1]), "+f"(d[2]), "+f"(d[3])
        : "r"(a[0]), "r"(a[1]), "r"(a[2]), "r"(a[3]),
          "r"(b[0]), "r"(b[1]));
}

__global__ void __launch_bounds__(256, 2)
gemm_kernel(const float* __restrict__ W,
            const float* __restrict__ bias,
            float* __restrict__ out) {
    __shared__ uint32_t Xs[GBM * XS_STRIDE];   // [m][k] tf32 bits
    __shared__ uint32_t Ws[GBK * WS_STRIDE];   // [k][n] tf32 bits

    const int tid  = threadIdx.x;
    const int warp = tid >> 5;
    const int lane = tid & 31;
    const int g    = lane >> 2;   // group id 0..7
    const int t    = lane & 3;    // thread-in-group 0..3
    const int wm   = (warp >> 1) * 32;   // warp m offset (0,32,64,96)
    const int wn   = (warp & 1) * 64;    // warp n offset (0,64)
    const int block_row = blockIdx.x * GBM;

    float acc[2][8][4];
#pragma unroll
    for (int mt = 0; mt < 2; mt++)
#pragma unroll
        for (int nt = 0; nt < 8; nt++)
#pragma unroll
            for (int r = 0; r < 4; r++) acc[mt][nt][r] = 0.0f;

    for (int k0 = 0; k0 < D; k0 += GBK) {
        // --- load X tile: 128 rows x 32 cols = 1024 float4; 4 per thread ---
#pragma unroll
        for (int it = 0; it < 4; it++) {
            int i   = tid + it * 256;
            int r   = i >> 3;        // 0..127
            int c4  = i & 7;         // 0..7
            int row = block_row + r;
            float4 v = make_float4(0.f, 0.f, 0.f, 0.f);
            if (row < N_NODES)
                v = *reinterpret_cast<const float4*>(g_acc + (size_t)row * D + k0 + c4 * 4);
            uint32_t* dst = &Xs[r * XS_STRIDE + c4 * 4];
            dst[0] = f2tf32(v.x); dst[1] = f2tf32(v.y);
            dst[2] = f2tf32(v.z); dst[3] = f2tf32(v.w);
        }
        // --- load W tile transposed: W[j][k0+k] -> Ws[k][j] ---
#pragma unroll
        for (int it = 0; it < 4; it++) {
            int i  = tid + it * 256;
            int j  = i >> 3;         // 0..127
            int c4 = i & 7;          // 0..7
            float4 v = *reinterpret_cast<const float4*>(W + j * D + k0 + c4 * 4);
            Ws[(c4 * 4 + 0) * WS_STRIDE + j] = f2tf32(v.x);
            Ws[(c4 * 4 + 1) * WS_STRIDE + j] = f2tf32(v.y);
            Ws[(c4 * 4 + 2) * WS_STRIDE + j] = f2tf32(v.z);
            Ws[(c4 * 4 + 3) * WS_STRIDE + j] = f2tf32(v.w);
        }
        __syncthreads();

#pragma unroll
        for (int ks = 0; ks < GBK; ks += 8) {
            // A fragments for 2 m-subtiles
            uint32_t afrag[2][4];
#pragma unroll
            for (int mt = 0; mt < 2; mt++) {
                int rbase = wm + mt * 16;
                afrag[mt][0] = Xs[(rbase + g    ) * XS_STRIDE + ks + t    ];
                afrag[mt][1] = Xs[(rbase + g + 8) * XS_STRIDE + ks + t    ];
                afrag[mt][2] = Xs[(rbase + g    ) * XS_STRIDE + ks + t + 4];
                afrag[mt][3] = Xs[(rbase + g + 8) * XS_STRIDE + ks + t + 4];
            }
            // B fragments for 8 n-subtiles, then MMAs
#pragma unroll
            for (int nt = 0; nt < 8; nt++) {
                uint32_t bfrag[2];
                int nb = wn + nt * 8 + g;
                bfrag[0] = Ws[(ks + t    ) * WS_STRIDE + nb];
                bfrag[1] = Ws[(ks + t + 4) * WS_STRIDE + nb];
                mma_tf32(acc[0][nt], afrag[0], bfrag);
                mma_tf32(acc[1][nt], afrag[1], bfrag);
            }
        }
        __syncthreads();
    }

    // --- epilogue: + bias, leaky relu, store ---
#pragma unroll
    for (int mt = 0; mt < 2; mt++) {
        int row0 = block_row + wm + mt * 16 + g;
#pragma unroll
        for (int nt = 0; nt < 8; nt++) {
            int col = wn + nt * 8 + t * 2;
            float2 bv = *reinterpret_cast<const float2*>(bias + col);
            float2 o;
            if (row0 < N_NODES) {
                o.x = acc[mt][nt][0] + bv.x;
                o.y = acc[mt][nt][1] + bv.y;
                o.x = o.x > 0.f ? o.x : 0.01f * o.x;
                o.y = o.y > 0.f ? o.y : 0.01f * o.y;
                *reinterpret_cast<float2*>(out + (size_t)row0 * D + col) = o;
            }
            int row1 = row0 + 8;
            if (row1 < N_NODES) {
                o.x = acc[mt][nt][2] + bv.x;
                o.y = acc[mt][nt][3] + bv.y;
                o.x = o.x > 0.f ? o.x : 0.01f * o.x;
                o.y = o.y > 0.f ? o.y : 0.01f * o.y;
                *reinterpret_cast<float2*>(out + (size_t)row1 * D + col) = o;
            }
        }
    }
}

// ---------------------------------------------------------------------------
extern "C" void kernel_launch(void* const* d_in, const int* in_sizes, int n_in,
                              void* d_out, int out_size) {
    const float* ego = (const float*)d_in[0];   // [100000,128] f32
    const void*  ei  = d_in[1];                 // [2,1600000] i32 or i64
    const float* ew  = (const float*)d_in[2];   // [1600000] f32
    const float* W   = (const float*)d_in[3];   // [128,128] f32
    const float* b   = (const float*)d_in[4];   // [128] f32
    float* out = (float*)d_out;

    // 0) detect index dtype (1 warp)
    detect_kernel<<<1, 32>>>((const long long*)ei);
    // 1) acc = ego
    {
        int n4 = N_NODES * D / 4;
        init_acc_kernel<<<(n4 + 255) / 256, 256>>>(ego);
    }
    // 2) scatter-add messages
    {
        long long total = (long long)N_EDGES * 32;
        int blocks = (int)((total + 255) / 256);
        scatter_kernel<<<blocks, 256>>>(ego, ei, ew);
    }
    // 3) GEMM + bias + leaky relu (tf32 tensor cores)
    {
        int blocks = (N_NODES + GBM - 1) / GBM;
        gemm_kernel<<<blocks, 256>>>(W, b, out);
    }
}

// round 4
// speedup vs baseline: 1.6545x; 1.3639x over previous
#include <cuda_runtime.h>
#include <cuda_bf16.h>
#include <cstdint>

#define N_NODES 100000
#define N_EDGES 1600000
#define D 128
#define SCAN_BLK 1024
#define N_SCAN_BLKS ((N_NODES + SCAN_BLK - 1) / SCAN_BLK)   // 98

// Scratch (static __device__ per allocation rules)
__device__ float g_acc[N_NODES * D];                  // ego + side
__device__ int   g_cnt[N_NODES];                      // histogram, then cursor
__device__ int   g_rowptr[N_NODES + 1];
__device__ int   g_bsum[N_SCAN_BLKS];
__device__ int   g_bsumx[N_SCAN_BLKS];
__device__ unsigned long long g_edges[N_EDGES];       // packed (w_bits<<32)|src
__device__ int   g_is64;

// ---------------------------------------------------------------------------
// 0) detect edge_index dtype (JAX w/o x64 silently emits int32).
// ---------------------------------------------------------------------------
__global__ void detect_kernel(const long long* __restrict__ ei) {
    long long v = ei[threadIdx.x];
    unsigned bad = __ballot_sync(0xffffffffu,
                                 (unsigned long long)v >= (unsigned long long)N_NODES);
    if (threadIdx.x == 0) g_is64 = (bad == 0u);
}

// ---------------------------------------------------------------------------
// 1) zero histogram
// ---------------------------------------------------------------------------
__global__ void zero_cnt_kernel() {
    int i = blockIdx.x * blockDim.x + threadIdx.x;
    if (i < N_NODES) g_cnt[i] = 0;
}

// ---------------------------------------------------------------------------
// 2) histogram of dst
// ---------------------------------------------------------------------------
__global__ void hist_kernel(const void* __restrict__ edge_index) {
    int e = blockIdx.x * blockDim.x + threadIdx.x;
    if (e >= N_EDGES) return;
    long long dst = g_is64 ? ((const long long*)edge_index)[e]
                           : (long long)((const int*)edge_index)[e];
    if ((unsigned long long)dst < N_NODES)
        atomicAdd(&g_cnt[(int)dst], 1);
}

// ---------------------------------------------------------------------------
// 3) exclusive scan (3 kernels): per-block scan, block-sum scan, add offsets
// ---------------------------------------------------------------------------
__global__ void scan1_kernel() {
    __shared__ int s[SCAN_BLK];
    int tid = threadIdx.x;
    int i = blockIdx.x * SCAN_BLK + tid;
    int v = (i < N_NODES) ? g_cnt[i] : 0;
    s[tid] = v;
    __syncthreads();
#pragma unroll
    for (int off = 1; off < SCAN_BLK; off <<= 1) {
        int t = (tid >= off) ? s[tid - off] : 0;
        __syncthreads();
        s[tid] += t;
        __syncthreads();
    }
    if (i < N_NODES) g_rowptr[i] = s[tid] - v;     // exclusive
    if (tid == SCAN_BLK - 1) g_bsum[blockIdx.x] = s[tid];
}

__global__ void scan2_kernel() {
    __shared__ int s[128];
    int tid = threadIdx.x;   // 128 threads, N_SCAN_BLKS <= 128
    int v = (tid < N_SCAN_BLKS) ? g_bsum[tid] : 0;
    s[tid] = v;
    __syncthreads();
#pragma unroll
    for (int off = 1; off < 128; off <<= 1) {
        int t = (tid >= off) ? s[tid - off] : 0;
        __syncthreads();
        s[tid] += t;
        __syncthreads();
    }
    if (tid < N_SCAN_BLKS) g_bsumx[tid] = s[tid] - v;
}

__global__ void scan3_kernel() {
    int i = blockIdx.x * blockDim.x + threadIdx.x;
    if (i < N_NODES) {
        g_rowptr[i] += g_bsumx[i >> 10];
        g_cnt[i] = 0;                     // reset -> cursor for fill
    }
    if (i == 0) g_rowptr[N_NODES] = N_EDGES;
}

// ---------------------------------------------------------------------------
// 4) fill CSR buckets with packed (weight, src) records
// ---------------------------------------------------------------------------
__global__ void fill_kernel(const void* __restrict__ edge_index,
                            const float* __restrict__ edge_weight) {
    int e = blockIdx.x * blockDim.x + threadIdx.x;
    if (e >= N_EDGES) return;
    long long dst, src;
    if (g_is64) {
        const long long* p = (const long long*)edge_index;
        dst = __ldcs(p + e);
        src = __ldcs(p + N_EDGES + e);
    } else {
        const int* p = (const int*)edge_index;
        dst = __ldcs(p + e);
        src = __ldcs(p + N_EDGES + e);
    }
    if ((unsigned long long)dst >= N_NODES ||
        (unsigned long long)src >= N_NODES) return;
    float w = __ldcs(edge_weight + e);
    int pos = g_rowptr[(int)dst] + atomicAdd(&g_cnt[(int)dst], 1);
    unsigned long long pk =
        ((unsigned long long)__float_as_uint(w) << 32) | (unsigned int)src;
    g_edges[pos] = pk;
}

// ---------------------------------------------------------------------------
// 5) gather: one warp per node. acc[i] = ego[i] + sum_e w_e * ego[src_e].
//    No atomics; each acc row written exactly once.
// ---------------------------------------------------------------------------
__global__ void __launch_bounds__(256)
gather_kernel(const float* __restrict__ ego) {
    int gid  = blockIdx.x * blockDim.x + threadIdx.x;
    int lane = gid & 31;
    int node = gid >> 5;
    if (node >= N_NODES) return;

    int beg = g_rowptr[node];
    int end = g_rowptr[node + 1];

    float4 a = *reinterpret_cast<const float4*>(ego + (size_t)node * D + lane * 4);

    for (int e = beg; e < end; e++) {
        unsigned long long pk = g_edges[e];                 // warp broadcast
        int   src = (int)(pk & 0xffffffffu);
        float w   = __uint_as_float((unsigned)(pk >> 32));
        const float4 v =
            *reinterpret_cast<const float4*>(ego + (size_t)src * D + lane * 4);
        a.x = fmaf(w, v.x, a.x);
        a.y = fmaf(w, v.y, a.y);
        a.z = fmaf(w, v.z, a.z);
        a.w = fmaf(w, v.w, a.w);
    }
    *reinterpret_cast<float4*>(g_acc + (size_t)node * D + lane * 4) = a;
}

// ---------------------------------------------------------------------------
// 6) GEMM: out = leaky_relu(acc @ W^T + b) via tf32 mma.sync (unchanged)
// ---------------------------------------------------------------------------
#define GBM 128
#define GBK 32
#define XS_STRIDE 36
#define WS_STRIDE 136

__device__ __forceinline__ uint32_t f2tf32(float f) {
    uint32_t u;
    asm("cvt.rna.tf32.f32 %0, %1;" : "=r"(u) : "f"(f));
    return u;
}

__device__ __forceinline__ void mma_tf32(float d[4], const uint32_t a[4],
                                         const uint32_t b[2]) {
    asm volatile(
        "mma.sync.aligned.m16n8k8.row.col.f32.tf32.tf32.f32 "
        "{%0,%1,%2,%3}, {%4,%5,%6,%7}, {%8,%9}, {%0,%1,%2,%3};"
        : "+f"(d[0]), "+f"(d[1]), "+f"(d[2]), "+f"(d[3])
        : "r"(a[0]), "r"(a[1]), "r"(a[2]), "r"(a[3]),
          "r"(b[0]), "r"(b[1]));
}

__global__ void __launch_bounds__(256, 2)
gemm_kernel(const float* __restrict__ W,
            const float* __restrict__ bias,
            float* __restrict__ out) {
    __shared__ uint32_t Xs[GBM * XS_STRIDE];
    __shared__ uint32_t Ws[GBK * WS_STRIDE];

    const int tid  = threadIdx.x;
    const int warp = tid >> 5;
    const int lane = tid & 31;
    const int g    = lane >> 2;
    const int t    = lane & 3;
    const int wm   = (warp >> 1) * 32;
    const int wn   = (warp & 1) * 64;
    const int block_row = blockIdx.x * GBM;

    float acc[2][8][4];
#pragma unroll
    for (int mt = 0; mt < 2; mt++)
#pragma unroll
        for (int nt = 0; nt < 8; nt++)
#pragma unroll
            for (int r = 0; r < 4; r++) acc[mt][nt][r] = 0.0f;

    for (int k0 = 0; k0 < D; k0 += GBK) {
#pragma unroll
        for (int it = 0; it < 4; it++) {
            int i   = tid + it * 256;
            int r   = i >> 3;
            int c4  = i & 7;
            int row = block_row + r;
            float4 v = make_float4(0.f, 0.f, 0.f, 0.f);
            if (row < N_NODES)
                v = *reinterpret_cast<const float4*>(g_acc + (size_t)row * D + k0 + c4 * 4);
            uint32_t* dst = &Xs[r * XS_STRIDE + c4 * 4];
            dst[0] = f2tf32(v.x); dst[1] = f2tf32(v.y);
            dst[2] = f2tf32(v.z); dst[3] = f2tf32(v.w);
        }
#pragma unroll
        for (int it = 0; it < 4; it++) {
            int i  = tid + it * 256;
            int j  = i >> 3;
            int c4 = i & 7;
            float4 v = *reinterpret_cast<const float4*>(W + j * D + k0 + c4 * 4);
            Ws[(c4 * 4 + 0) * WS_STRIDE + j] = f2tf32(v.x);
            Ws[(c4 * 4 + 1) * WS_STRIDE + j] = f2tf32(v.y);
            Ws[(c4 * 4 + 2) * WS_STRIDE + j] = f2tf32(v.z);
            Ws[(c4 * 4 + 3) * WS_STRIDE + j] = f2tf32(v.w);
        }
        __syncthreads();

#pragma unroll
        for (int ks = 0; ks < GBK; ks += 8) {
            uint32_t afrag[2][4];
#pragma unroll
            for (int mt = 0; mt < 2; mt++) {
                int rbase = wm + mt * 16;
                afrag[mt][0] = Xs[(rbase + g    ) * XS_STRIDE + ks + t    ];
                afrag[mt][1] = Xs[(rbase + g + 8) * XS_STRIDE + ks + t    ];
                afrag[mt][2] = Xs[(rbase + g    ) * XS_STRIDE + ks + t + 4];
                afrag[mt][3] = Xs[(rbase + g + 8) * XS_STRIDE + ks + t + 4];
            }
#pragma unroll
            for (int nt = 0; nt < 8; nt++) {
                uint32_t bfrag[2];
                int nb = wn + nt * 8 + g;
                bfrag[0] = Ws[(ks + t    ) * WS_STRIDE + nb];
                bfrag[1] = Ws[(ks + t + 4) * WS_STRIDE + nb];
                mma_tf32(acc[0][nt], afrag[0], bfrag);
                mma_tf32(acc[1][nt], afrag[1], bfrag);
            }
        }
        __syncthreads();
    }

#pragma unroll
    for (int mt = 0; mt < 2; mt++) {
        int row0 = block_row + wm + mt * 16 + g;
#pragma unroll
        for (int nt = 0; nt < 8; nt++) {
            int col = wn + nt * 8 + t * 2;
            float2 bv = *reinterpret_cast<const float2*>(bias + col);
            float2 o;
            if (row0 < N_NODES) {
                o.x = acc[mt][nt][0] + bv.x;
                o.y = acc[mt][nt][1] + bv.y;
                o.x = o.x > 0.f ? o.x : 0.01f * o.x;
                o.y = o.y > 0.f ? o.y : 0.01f * o.y;
                *reinterpret_cast<float2*>(out + (size_t)row0 * D + col) = o;
            }
            int row1 = row0 + 8;
            if (row1 < N_NODES) {
                o.x = acc[mt][nt][2] + bv.x;
                o.y = acc[mt][nt][3] + bv.y;
                o.x = o.x > 0.f ? o.x : 0.01f * o.x;
                o.y = o.y > 0.f ? o.y : 0.01f * o.y;
                *reinterpret_cast<float2*>(out + (size_t)row1 * D + col) = o;
            }
        }
    }
}

// ---------------------------------------------------------------------------
extern "C" void kernel_launch(void* const* d_in, const int* in_sizes, int n_in,
                              void* d_out, int out_size) {
    const float* ego = (const float*)d_in[0];
    const void*  ei  = d_in[1];
    const float* ew  = (const float*)d_in[2];
    const float* W   = (const float*)d_in[3];
    const float* b   = (const float*)d_in[4];
    float* out = (float*)d_out;

    const int EBLK = (N_EDGES + 255) / 256;
    const int NBLK = (N_NODES + 255) / 256;

    detect_kernel<<<1, 32>>>((const long long*)ei);
    zero_cnt_kernel<<<NBLK, 256>>>();
    hist_kernel<<<EBLK, 256>>>(ei);
    scan1_kernel<<<N_SCAN_BLKS, SCAN_BLK>>>();
    scan2_kernel<<<1, 128>>>();
    scan3_kernel<<<NBLK, 256>>>();
    fill_kernel<<<EBLK, 256>>>(ei, ew);
    {
        long long total = (long long)N_NODES * 32;
        int blocks = (int)((total + 255) / 256);
        gather_kernel<<<blocks, 256>>>(ego);
    }
    {
        int blocks = (N_NODES + GBM - 1) / GBM;
        gemm_kernel<<<blocks, 256>>>(W, b, out);
    }
}

// round 5
// speedup vs baseline: 2.3284x; 1.4073x over previous
#include <cuda_runtime.h>
#include <cuda_bf16.h>
#include <cstdint>

#define N_NODES 100000
#define N_EDGES 1600000
#define D 128
#define SCAN_BLK 1024
#define N_SCAN_BLKS ((N_NODES + SCAN_BLK - 1) / SCAN_BLK)   // 98

// Scratch (static __device__ per allocation rules)
__device__ float g_acc[N_NODES * D];                  // ego + side (tf32-rounded)
__device__ int   g_cnt[N_NODES];                      // histogram, then cursor
__device__ int   g_rowptr[N_NODES + 1];
__device__ int   g_bsum[N_SCAN_BLKS];
__device__ int   g_bsumx[N_SCAN_BLKS];
__device__ unsigned long long g_edges[N_EDGES];       // packed (w_bits<<32)|src
__device__ int   g_is64;

__device__ __forceinline__ uint32_t f2tf32(float f) {
    uint32_t u;
    asm("cvt.rna.tf32.f32 %0, %1;" : "=r"(u) : "f"(f));
    return u;
}

// ---------------------------------------------------------------------------
// 0) detect edge_index dtype (JAX w/o x64 silently emits int32).
// ---------------------------------------------------------------------------
__global__ void detect_kernel(const long long* __restrict__ ei) {
    long long v = ei[threadIdx.x];
    unsigned bad = __ballot_sync(0xffffffffu,
                                 (unsigned long long)v >= (unsigned long long)N_NODES);
    if (threadIdx.x == 0) g_is64 = (bad == 0u);
}

// ---------------------------------------------------------------------------
// 1) zero histogram
// ---------------------------------------------------------------------------
__global__ void zero_cnt_kernel() {
    int i = blockIdx.x * blockDim.x + threadIdx.x;
    if (i < N_NODES) g_cnt[i] = 0;
}

// ---------------------------------------------------------------------------
// 2) histogram of dst
// ---------------------------------------------------------------------------
__global__ void hist_kernel(const void* __restrict__ edge_index) {
    int e = blockIdx.x * blockDim.x + threadIdx.x;
    if (e >= N_EDGES) return;
    long long dst = g_is64 ? ((const long long*)edge_index)[e]
                           : (long long)((const int*)edge_index)[e];
    if ((unsigned long long)dst < N_NODES)
        atomicAdd(&g_cnt[(int)dst], 1);
}

// ---------------------------------------------------------------------------
// 3) exclusive scan (3 kernels). scan1 = warp-shuffle scan.
// ---------------------------------------------------------------------------
__global__ void scan1_kernel() {
    __shared__ int wsum[32];
    int tid  = threadIdx.x;
    int lane = tid & 31;
    int wid  = tid >> 5;
    int i = blockIdx.x * SCAN_BLK + tid;
    int v = (i < N_NODES) ? g_cnt[i] : 0;

    int x = v;
#pragma unroll
    for (int off = 1; off < 32; off <<= 1) {
        int t = __shfl_up_sync(0xffffffffu, x, off);
        if (lane >= off) x += t;
    }
    if (lane == 31) wsum[wid] = x;
    __syncthreads();
    if (wid == 0) {
        int y = wsum[lane];
#pragma unroll
        for (int off = 1; off < 32; off <<= 1) {
            int t = __shfl_up_sync(0xffffffffu, y, off);
            if (lane >= off) y += t;
        }
        wsum[lane] = y;
    }
    __syncthreads();
    int inc = x + (wid > 0 ? wsum[wid - 1] : 0);
    if (i < N_NODES) g_rowptr[i] = inc - v;                // exclusive
    if (tid == SCAN_BLK - 1) g_bsum[blockIdx.x] = inc;
}

__global__ void scan2_kernel() {
    __shared__ int s[128];
    int tid = threadIdx.x;   // 128 threads, N_SCAN_BLKS <= 128
    int v = (tid < N_SCAN_BLKS) ? g_bsum[tid] : 0;
    s[tid] = v;
    __syncthreads();
#pragma unroll
    for (int off = 1; off < 128; off <<= 1) {
        int t = (tid >= off) ? s[tid - off] : 0;
        __syncthreads();
        s[tid] += t;
        __syncthreads();
    }
    if (tid < N_SCAN_BLKS) g_bsumx[tid] = s[tid] - v;
}

__global__ void scan3_kernel() {
    int i = blockIdx.x * blockDim.x + threadIdx.x;
    if (i < N_NODES) {
        g_rowptr[i] += g_bsumx[i >> 10];
        g_cnt[i] = 0;                     // reset -> cursor for fill
    }
    if (i == 0) g_rowptr[N_NODES] = N_EDGES;
}

// ---------------------------------------------------------------------------
// 4) fill CSR buckets with packed (weight, src) records
// ---------------------------------------------------------------------------
__global__ void fill_kernel(const void* __restrict__ edge_index,
                            const float* __restrict__ edge_weight) {
    int e = blockIdx.x * blockDim.x + threadIdx.x;
    if (e >= N_EDGES) return;
    long long dst, src;
    if (g_is64) {
        const long long* p = (const long long*)edge_index;
        dst = __ldcs(p + e);
        src = __ldcs(p + N_EDGES + e);
    } else {
        const int* p = (const int*)edge_index;
        dst = __ldcs(p + e);
        src = __ldcs(p + N_EDGES + e);
    }
    if ((unsigned long long)dst >= N_NODES ||
        (unsigned long long)src >= N_NODES) return;
    float w = __ldcs(edge_weight + e);
    int pos = g_rowptr[(int)dst] + atomicAdd(&g_cnt[(int)dst], 1);
    unsigned long long pk =
        ((unsigned long long)__float_as_uint(w) << 32) | (unsigned int)src;
    g_edges[pos] = pk;
}

// ---------------------------------------------------------------------------
// 5) gather: one warp per node. acc[i] = tf32(ego[i] + sum_e w_e*ego[src_e]).
//    Chunked edge loading: lanes cooperatively fetch 32 packed records with
//    one coalesced 8B load each, then an unrolled shfl-broadcast loop issues
//    4 independent row loads per step (MLP ~4 per warp, no atomics).
// ---------------------------------------------------------------------------
__global__ void __launch_bounds__(256)
gather_kernel(const float* __restrict__ ego) {
    int gid  = blockIdx.x * blockDim.x + threadIdx.x;
    int lane = gid & 31;
    int node = gid >> 5;
    if (node >= N_NODES) return;

    int beg = g_rowptr[node];
    int end = g_rowptr[node + 1];

    float4 a = *reinterpret_cast<const float4*>(ego + (size_t)node * D + lane * 4);

    int e = beg;
    // full chunks of 32
    while (e + 32 <= end) {
        unsigned long long pk = __ldcs(g_edges + e + lane);
#pragma unroll
        for (int j0 = 0; j0 < 32; j0 += 4) {
            float4 v[4];
            float  w[4];
#pragma unroll
            for (int jj = 0; jj < 4; jj++) {
                unsigned long long p = __shfl_sync(0xffffffffu, pk, j0 + jj);
                int src = (int)(p & 0xffffffffu);
                w[jj]   = __uint_as_float((unsigned)(p >> 32));
                v[jj]   = *reinterpret_cast<const float4*>(
                              ego + (size_t)src * D + lane * 4);
            }
#pragma unroll
            for (int jj = 0; jj < 4; jj++) {
                a.x = fmaf(w[jj], v[jj].x, a.x);
                a.y = fmaf(w[jj], v[jj].y, a.y);
                a.z = fmaf(w[jj], v[jj].z, a.z);
                a.w = fmaf(w[jj], v[jj].w, a.w);
            }
        }
        e += 32;
    }
    // remainder (< 32 edges)
    int n = end - e;
    if (n > 0) {
        unsigned long long pk = (lane < n) ? __ldcs(g_edges + e + lane) : 0ull;
        for (int j = 0; j < n; j++) {
            unsigned long long p = __shfl_sync(0xffffffffu, pk, j);
            int src = (int)(p & 0xffffffffu);
            float w = __uint_as_float((unsigned)(p >> 32));
            const float4 v = *reinterpret_cast<const float4*>(
                                 ego + (size_t)src * D + lane * 4);
            a.x = fmaf(w, v.x, a.x);
            a.y = fmaf(w, v.y, a.y);
            a.z = fmaf(w, v.z, a.z);
            a.w = fmaf(w, v.w, a.w);
        }
    }
    // store tf32-rounded bits (GEMM consumes these directly)
    uint4 o;
    o.x = f2tf32(a.x); o.y = f2tf32(a.y);
    o.z = f2tf32(a.z); o.w = f2tf32(a.w);
    *reinterpret_cast<uint4*>(g_acc + (size_t)node * D + lane * 4) = o;
}

// ---------------------------------------------------------------------------
// 6) GEMM: out = leaky_relu(acc @ W^T + b), tf32 mma.sync.
//    Whole W (tf32, transposed) resident in smem; X tiles double-buffered
//    via cp.async.cg (g_acc already holds tf32 bits, so byte-copy is exact).
// ---------------------------------------------------------------------------
#define GBM 128
#define GBK 32
#define XS_STRIDE 36
#define WS_STRIDE 136
#define XS_TILE (GBM * XS_STRIDE)                       // u32 per X buffer
#define GEMM_SMEM_BYTES ((128 * WS_STRIDE + 2 * XS_TILE) * 4)   // 106496 B

__device__ __forceinline__ void mma_tf32(float d[4], const uint32_t a[4],
                                         const uint32_t b[2]) {
    asm volatile(
        "mma.sync.aligned.m16n8k8.row.col.f32.tf32.tf32.f32 "
        "{%0,%1,%2,%3}, {%4,%5,%6,%7}, {%8,%9}, {%0,%1,%2,%3};"
        : "+f"(d[0]), "+f"(d[1]), "+f"(d[2]), "+f"(d[3])
        : "r"(a[0]), "r"(a[1]), "r"(a[2]), "r"(a[3]),
          "r"(b[0]), "r"(b[1]));
}

__device__ __forceinline__ void cp_async16(uint32_t smem_addr,
                                           const void* gptr, int src_bytes) {
    asm volatile("cp.async.cg.shared.global [%0], [%1], 16, %2;"
                 :: "r"(smem_addr), "l"(gptr), "r"(src_bytes));
}
__device__ __forceinline__ void cp_commit() {
    asm volatile("cp.async.commit_group;");
}
template <int N>
__device__ __forceinline__ void cp_wait() {
    asm volatile("cp.async.wait_group %0;" :: "n"(N));
}

// issue one X tile (128 rows x 32 floats) into buffer `buf`
__device__ __forceinline__ void issue_x_tile(uint32_t xs_base_u32, int buf,
                                             int block_row, int k0, int tid) {
#pragma unroll
    for (int it = 0; it < 4; it++) {
        int i   = tid + it * 256;
        int r   = i >> 3;          // 0..127
        int c4  = i & 7;           // 0..7
        int row = block_row + r;
        int ok  = (row < N_NODES);
        int rc  = ok ? row : (N_NODES - 1);
        const void* g = g_acc + (size_t)rc * D + k0 + c4 * 4;
        uint32_t s = xs_base_u32 + (buf * XS_TILE + r * XS_STRIDE + c4 * 4) * 4;
        cp_async16(s, g, ok ? 16 : 0);   // src_bytes=0 zero-fills
    }
    cp_commit();
}

__global__ void __launch_bounds__(256, 2)
gemm_kernel(const float* __restrict__ W,
            const float* __restrict__ bias,
            float* __restrict__ out) {
    extern __shared__ uint32_t smem_u[];
    uint32_t* Ws = smem_u;                       // [k][j], k=0..127, stride 136
    uint32_t* Xs = smem_u + 128 * WS_STRIDE;     // 2 buffers of [r][k] (32 k)
    const uint32_t xs_u32 =
        (uint32_t)__cvta_generic_to_shared(Xs);

    const int tid  = threadIdx.x;
    const int warp = tid >> 5;
    const int lane = tid & 31;
    const int g    = lane >> 2;
    const int t    = lane & 3;
    const int wm   = (warp >> 1) * 32;
    const int wn   = (warp & 1) * 64;
    const int block_row = blockIdx.x * GBM;

    // prologue: start X tile 0, then load+convert whole W (overlapped)
    issue_x_tile(xs_u32, 0, block_row, 0, tid);
#pragma unroll
    for (int it = 0; it < 16; it++) {
        int i  = tid + it * 256;     // 0..4095 over 4096 float4
        int c4 = i >> 7;             // 0..31
        int j  = i & 127;            // 0..127  (lane-consecutive: STS conflict-free)
        float4 v = *reinterpret_cast<const float4*>(W + j * D + c4 * 4);
        Ws[(c4 * 4 + 0) * WS_STRIDE + j] = f2tf32(v.x);
        Ws[(c4 * 4 + 1) * WS_STRIDE + j] = f2tf32(v.y);
        Ws[(c4 * 4 + 2) * WS_STRIDE + j] = f2tf32(v.z);
        Ws[(c4 * 4 + 3) * WS_STRIDE + j] = f2tf32(v.w);
    }

    float acc[2][8][4];
#pragma unroll
    for (int mt = 0; mt < 2; mt++)
#pragma unroll
        for (int nt = 0; nt < 8; nt++)
#pragma unroll
            for (int r = 0; r < 4; r++) acc[mt][nt][r] = 0.0f;

#pragma unroll
    for (int k0t = 0; k0t < 4; k0t++) {
        __syncthreads();   // previous compute done (and W stores visible, iter 0)
        if (k0t < 3)
            issue_x_tile(xs_u32, (k0t + 1) & 1, block_row, (k0t + 1) * GBK, tid);
        if (k0t < 3) cp_wait<1>(); else cp_wait<0>();
        __syncthreads();   // current tile visible to all warps

        const uint32_t* Xb = Xs + (k0t & 1) * XS_TILE;
#pragma unroll
        for (int ks = 0; ks < GBK; ks += 8) {
            uint32_t afrag[2][4];
#pragma unroll
            for (int mt = 0; mt < 2; mt++) {
                int rbase = wm + mt * 16;
                afrag[mt][0] = Xb[(rbase + g    ) * XS_STRIDE + ks + t    ];
                afrag[mt][1] = Xb[(rbase + g + 8) * XS_STRIDE + ks + t    ];
                afrag[mt][2] = Xb[(rbase + g    ) * XS_STRIDE + ks + t + 4];
                afrag[mt][3] = Xb[(rbase + g + 8) * XS_STRIDE + ks + t + 4];
            }
            int kg = k0t * GBK + ks;
#pragma unroll
            for (int nt = 0; nt < 8; nt++) {
                uint32_t bfrag[2];
                int nb = wn + nt * 8 + g;
                bfrag[0] = Ws[(kg + t    ) * WS_STRIDE + nb];
                bfrag[1] = Ws[(kg + t + 4) * WS_STRIDE + nb];
                mma_tf32(acc[0][nt], afrag[0], bfrag);
                mma_tf32(acc[1][nt], afrag[1], bfrag);
            }
        }
    }

    // epilogue: + bias, leaky relu, store
#pragma unroll
    for (int mt = 0; mt < 2; mt++) {
        int row0 = block_row + wm + mt * 16 + g;
#pragma unroll
        for (int nt = 0; nt < 8; nt++) {
            int col = wn + nt * 8 + t * 2;
            float2 bv = *reinterpret_cast<const float2*>(bias + col);
            float2 o;
            if (row0 < N_NODES) {
                o.x = acc[mt][nt][0] + bv.x;
                o.y = acc[mt][nt][1] + bv.y;
                o.x = o.x > 0.f ? o.x : 0.01f * o.x;
                o.y = o.y > 0.f ? o.y : 0.01f * o.y;
                *reinterpret_cast<float2*>(out + (size_t)row0 * D + col) = o;
            }
            int row1 = row0 + 8;
            if (row1 < N_NODES) {
                o.x = acc[mt][nt][2] + bv.x;
                o.y = acc[mt][nt][3] + bv.y;
                o.x = o.x > 0.f ? o.x : 0.01f * o.x;
                o.y = o.y > 0.f ? o.y : 0.01f * o.y;
                *reinterpret_cast<float2*>(out + (size_t)row1 * D + col) = o;
            }
        }
    }
}

// ---------------------------------------------------------------------------
extern "C" void kernel_launch(void* const* d_in, const int* in_sizes, int n_in,
                              void* d_out, int out_size) {
    const float* ego = (const float*)d_in[0];
    const void*  ei  = d_in[1];
    const float* ew  = (const float*)d_in[2];
    const float* W   = (const float*)d_in[3];
    const float* b   = (const float*)d_in[4];
    float* out = (float*)d_out;

    const int EBLK = (N_EDGES + 255) / 256;
    const int NBLK = (N_NODES + 255) / 256;

    cudaFuncSetAttribute(gemm_kernel,
                         cudaFuncAttributeMaxDynamicSharedMemorySize,
                         GEMM_SMEM_BYTES);

    detect_kernel<<<1, 32>>>((const long long*)ei);
    zero_cnt_kernel<<<NBLK, 256>>>();
    hist_kernel<<<EBLK, 256>>>(ei);
    scan1_kernel<<<N_SCAN_BLKS, SCAN_BLK>>>();
    scan2_kernel<<<1, 128>>>();
    scan3_kernel<<<NBLK, 256>>>();
    fill_kernel<<<EBLK, 256>>>(ei, ew);
    {
        long long total = (long long)N_NODES * 32;
        int blocks = (int)((total + 255) / 256);
        gather_kernel<<<blocks, 256>>>(ego);
    }
    {
        int blocks = (N_NODES + GBM - 1) / GBM;
        gemm_kernel<<<blocks, 256, GEMM_SMEM_BYTES>>>(W, b, out);
    }
}